// round 5
// baseline (speedup 1.0000x reference)
#include <cuda_runtime.h>
#include <math.h>

#define NB 64
#define NP 8732
#define NO 32
#define NC 81
#define IMGSZ 224.0f
#define THRESH 0.5f

// ---------------- scratch (device globals; re-initialized every launch) ----
static __device__ unsigned long long g_objkey[NB * NO];   // packed (iou_bits<<32)|~p
static __device__ float          g_bestov[NB * NP];
static __device__ unsigned char  g_bestobj[NB * NP];
static __device__ unsigned char  g_label[NB * NP];
static __device__ float          g_ce[NB * NP];
static __device__ int            g_npos[NB];
static __device__ float          g_locsum[NB];
static __device__ float          g_contrib[NB];

// ---------------- helpers --------------------------------------------------
__device__ __forceinline__ float warp_sum_f(float v) {
#pragma unroll
    for (int s = 16; s; s >>= 1) v += __shfl_xor_sync(0xffffffffu, v, s);
    return v;
}
__device__ __forceinline__ int warp_sum_i(int v) {
#pragma unroll
    for (int s = 16; s; s >>= 1) v += __shfl_xor_sync(0xffffffffu, v, s);
    return v;
}
__device__ __forceinline__ float warp_max_f(float v) {
#pragma unroll
    for (int s = 16; s; s >>= 1) v = fmaxf(v, __shfl_xor_sync(0xffffffffu, v, s));
    return v;
}
__device__ __forceinline__ unsigned long long warp_max_ull(unsigned long long v) {
#pragma unroll
    for (int s = 16; s; s >>= 1) {
        unsigned long long o = __shfl_down_sync(0xffffffffu, v, s);
        v = (o > v) ? o : v;
    }
    return v;
}

// ---------------- K0: init scratch ----------------------------------------
__global__ void k_init() {
    int idx = blockIdx.x * blockDim.x + threadIdx.x;
    if (idx < NB * NO) g_objkey[idx] = 0ull;
    if (idx < NB) { g_npos[idx] = 0; g_locsum[idx] = 0.0f; }
}

// ---------------- K1: per-prior best object (argmax over O, first occ) -----
__global__ void k_prior_best(const float* __restrict__ gt_boxes,
                             const float* __restrict__ priors) {
    const int b = blockIdx.y;
    __shared__ float bx0[NO], by0[NO], bx1[NO], by1[NO], barea[NO];
    if (threadIdx.x < NO) {
        int o = threadIdx.x;
        const float* g = gt_boxes + (b * NO + o) * 4;
        float g0 = g[0], g1 = g[1], g2 = g[2], g3 = g[3];
        float x0 = g0 / IMGSZ, y0 = g1 / IMGSZ;
        float x1 = (g0 + g2) / IMGSZ, y1 = (g1 + g3) / IMGSZ;
        bx0[o] = x0; by0[o] = y0; bx1[o] = x1; by1[o] = y1;
        barea[o] = (x1 - x0) * (y1 - y0);
    }
    __syncthreads();

    const int stride = gridDim.x * blockDim.x;
    for (int p = blockIdx.x * blockDim.x + threadIdx.x; p < NP; p += stride) {
        float4 pr = ((const float4*)priors)[p];
        float px0 = pr.x - pr.z * 0.5f, py0 = pr.y - pr.w * 0.5f;
        float px1 = pr.x + pr.z * 0.5f, py1 = pr.y + pr.w * 0.5f;
        float parea = (px1 - px0) * (py1 - py0);
        float bv = -1.0f; int bo = 0;
#pragma unroll
        for (int o = 0; o < NO; o++) {
            float lx = fmaxf(bx0[o], px0), ly = fmaxf(by0[o], py0);
            float rx = fminf(bx1[o], px1), ry = fminf(by1[o], py1);
            float w = fmaxf(rx - lx, 0.0f), h = fmaxf(ry - ly, 0.0f);
            float inter = w * h;
            float iou = inter / (barea[o] + parea - inter);
            if (iou > bv) { bv = iou; bo = o; }
        }
        g_bestov[b * NP + p] = bv;
        g_bestobj[b * NP + p] = (unsigned char)bo;
    }
}

// ---------------- K2: per-object best prior (argmax over P, first occ) -----
// grid (8, NB), 256 threads = 8 warps; warp w handles objects w, w+8, w+16, w+24
// over a chunk of priors, then atomicMax of packed key into global (order-free).
#define OBJ_CS 1092
__global__ void k_obj_best(const float* __restrict__ gt_boxes,
                           const float* __restrict__ priors) {
    const int b = blockIdx.y;
    __shared__ float bx0[NO], by0[NO], bx1[NO], by1[NO], barea[NO];
    if (threadIdx.x < NO) {
        int o = threadIdx.x;
        const float* g = gt_boxes + (b * NO + o) * 4;
        float g0 = g[0], g1 = g[1], g2 = g[2], g3 = g[3];
        float x0 = g0 / IMGSZ, y0 = g1 / IMGSZ;
        float x1 = (g0 + g2) / IMGSZ, y1 = (g1 + g3) / IMGSZ;
        bx0[o] = x0; by0[o] = y0; bx1[o] = x1; by1[o] = y1;
        barea[o] = (x1 - x0) * (y1 - y0);
    }
    __syncthreads();

    const int lane = threadIdx.x & 31;
    const int w = threadIdx.x >> 5;
    const int p0 = blockIdx.x * OBJ_CS;
    const int pend = min(p0 + OBJ_CS, NP);

#pragma unroll
    for (int oo = 0; oo < 4; oo++) {
        const int o = w + oo * 8;
        const float ax0 = bx0[o], ay0 = by0[o], ax1 = bx1[o], ay1 = by1[o], aa = barea[o];
        unsigned long long key = 0ull;
        for (int p = p0 + lane; p < pend; p += 32) {
            float4 pr = ((const float4*)priors)[p];
            float px0 = pr.x - pr.z * 0.5f, py0 = pr.y - pr.w * 0.5f;
            float px1 = pr.x + pr.z * 0.5f, py1 = pr.y + pr.w * 0.5f;
            float parea = (px1 - px0) * (py1 - py0);
            float lx = fmaxf(ax0, px0), ly = fmaxf(ay0, py0);
            float rx = fminf(ax1, px1), ry = fminf(ay1, py1);
            float ww = fmaxf(rx - lx, 0.0f), hh = fmaxf(ry - ly, 0.0f);
            float inter = ww * hh;
            float iou = inter / (aa + parea - inter);
            unsigned long long k =
                ((unsigned long long)__float_as_uint(iou) << 32) |
                (unsigned long long)(0xffffffffu - (unsigned)p);
            if (k > key) key = k;
        }
        key = warp_max_ull(key);
        if (lane == 0) atomicMax(&g_objkey[b * NO + o], key);
    }
}

// ---------------- K3: labels + true_locs + SmoothL1 partials ---------------
__global__ void k_assemble(const float* __restrict__ gt_boxes,
                           const int* __restrict__ gt_labels,
                           const float* __restrict__ priors,
                           const float* __restrict__ pred_locs) {
    const int b = blockIdx.y;
    __shared__ float scx[NO], scy[NO], sww[NO], shh[NO];
    __shared__ int slab[NO], sforced[NO];
    __shared__ float s_loc[8];
    __shared__ int s_np[8];

    if (threadIdx.x < NO) {
        int o = threadIdx.x;
        const float* g = gt_boxes + (b * NO + o) * 4;
        float g0 = g[0], g1 = g[1], g2 = g[2], g3 = g[3];
        float x0 = g0 / IMGSZ, y0 = g1 / IMGSZ;
        float x1 = (g0 + g2) / IMGSZ, y1 = (g1 + g3) / IMGSZ;
        scx[o] = (x0 + x1) * 0.5f; scy[o] = (y0 + y1) * 0.5f;
        sww[o] = x1 - x0;          shh[o] = y1 - y0;
        slab[o] = gt_labels[b * NO + o];
        sforced[o] = (int)(0xffffffffu - (unsigned)(g_objkey[b * NO + o] & 0xffffffffull));
    }
    __syncthreads();

    float locacc = 0.0f;
    int npacc = 0;
    const int stride = gridDim.x * blockDim.x;
    for (int p = blockIdx.x * blockDim.x + threadIdx.x; p < NP; p += stride) {
        float ov = g_bestov[b * NP + p];
        int obj = g_bestobj[b * NP + p];
#pragma unroll
        for (int o = 0; o < NO; o++)
            if (sforced[o] == p) { obj = o; ov = 1.0f; }  // last o wins
        int lbl = (ov < THRESH) ? 0 : slab[obj];
        g_label[b * NP + p] = (unsigned char)lbl;
        if (lbl != 0) {
            npacc++;
            float4 pr = ((const float4*)priors)[p];
            float tcx = (scx[obj] - pr.x) / (pr.z / 10.0f);
            float tcy = (scy[obj] - pr.y) / (pr.w / 10.0f);
            float tw = logf(sww[obj] / pr.z) * 5.0f;
            float th = logf(shh[obj] / pr.w) * 5.0f;
            float4 pl = ((const float4*)pred_locs)[b * NP + p];
            float d, s = 0.0f;
            d = fabsf(pl.x - tcx); s += (d < 1.0f) ? 0.5f * d * d : d - 0.5f;
            d = fabsf(pl.y - tcy); s += (d < 1.0f) ? 0.5f * d * d : d - 0.5f;
            d = fabsf(pl.z - tw);  s += (d < 1.0f) ? 0.5f * d * d : d - 0.5f;
            d = fabsf(pl.w - th);  s += (d < 1.0f) ? 0.5f * d * d : d - 0.5f;
            locacc += s;
        }
    }
    locacc = warp_sum_f(locacc);
    npacc = warp_sum_i(npacc);
    int lane = threadIdx.x & 31, wid = threadIdx.x >> 5;
    if (lane == 0) { s_loc[wid] = locacc; s_np[wid] = npacc; }
    __syncthreads();
    if (threadIdx.x == 0) {
        float l = 0.0f; int n = 0;
        for (int k = 0; k < 8; k++) { l += s_loc[k]; n += s_np[k]; }
        atomicAdd(&g_locsum[b], l);
        atomicAdd(&g_npos[b], n);
    }
}

// ---------------- K4: per-(b,p) cross entropy (warp per row) ---------------
__global__ void k_ce(const float* __restrict__ scores) {
    const int gw = (blockIdx.x * blockDim.x + threadIdx.x) >> 5;
    const int lane = threadIdx.x & 31;
    if (gw >= NB * NP) return;
    const float* row = scores + (size_t)gw * NC;
    float x0 = row[lane];
    float x1 = row[lane + 32];                       // lane+32 <= 63 < 81 always
    bool v2 = (lane + 64) < NC;                      // lanes 0..16
    float x2 = v2 ? row[lane + 64] : -3.4e38f;
    float m = fmaxf(x0, fmaxf(x1, x2));
    m = warp_max_f(m);
    float e = __expf(x0 - m) + __expf(x1 - m) + (v2 ? __expf(x2 - m) : 0.0f);
    e = warp_sum_f(e);
    if (lane == 0) {
        int lbl = g_label[gw];
        g_ce[gw] = m + logf(e) - row[lbl];
    }
}

// ---------------- K5: per-image hard-negative top-K sum --------------------
__global__ void k_topk() {
    __shared__ float sce[NP];             // ce_neg (clamped >= 0)
    __shared__ float s_pos[8];
    __shared__ float s_gts[8];
    __shared__ int   s_gtc[8];
    __shared__ int   s_cnt[32];

    const int b = blockIdx.x;
    const int tid = threadIdx.x, lane = tid & 31, wid = tid >> 5;

    float posacc = 0.0f;
    for (int p = tid; p < NP; p += 256) {
        float c = g_ce[b * NP + p];
        if (g_label[b * NP + p]) { posacc += c; c = 0.0f; }
        else                      c = fmaxf(c, 0.0f);
        sce[p] = c;
    }
    posacc = warp_sum_f(posacc);
    if (lane == 0) s_pos[wid] = posacc;
    if (tid < 32) s_cnt[tid] = 0;
    __syncthreads();

    int np = g_npos[b];
    int K = 3 * max(np, 1);
    if (K > NP) K = NP;

    unsigned t = 0;
    for (int bit = 31; bit >= 0; bit--) {
        unsigned cand = t | (1u << bit);
        int c = 0;
        for (int p = tid; p < NP; p += 256)
            c += (__float_as_uint(sce[p]) >= cand) ? 1 : 0;
        c = warp_sum_i(c);
        if (lane == 0) atomicAdd(&s_cnt[bit], c);
        __syncthreads();
        if (s_cnt[bit] >= K) t = cand;
    }

    float sg = 0.0f; int cg = 0;
    for (int p = tid; p < NP; p += 256) {
        unsigned u = __float_as_uint(sce[p]);
        if (u > t) { sg += sce[p]; cg++; }
    }
    sg = warp_sum_f(sg);
    cg = warp_sum_i(cg);
    if (lane == 0) { s_gts[wid] = sg; s_gtc[wid] = cg; }
    __syncthreads();

    if (tid == 0) {
        float hard = 0.0f; int c = 0; float pos = 0.0f;
        for (int k = 0; k < 8; k++) { hard += s_gts[k]; c += s_gtc[k]; pos += s_pos[k]; }
        hard += (float)(K - c) * __uint_as_float(t);
        g_contrib[b] = pos + hard;
    }
}

// ---------------- K6: final scalar ----------------------------------------
__global__ void k_final(float* __restrict__ out) {
    if (threadIdx.x == 0 && blockIdx.x == 0) {
        float sumc = 0.0f, sumnpcl = 0.0f, suml = 0.0f;
        long long tp = 0;
        for (int b = 0; b < NB; b++) {
            sumc += g_contrib[b];
            int np = g_npos[b];
            tp += np;
            sumnpcl += (float)max(np, 1);
            suml += g_locsum[b];
        }
        float conf = sumc / sumnpcl;
        long long den = tp * 4; if (den < 1) den = 1;
        float loc = (tp > 0) ? (suml / (float)den) : 0.0f;
        out[0] = conf + loc;
    }
}

// ---------------- launch ---------------------------------------------------
extern "C" void kernel_launch(void* const* d_in, const int* in_sizes, int n_in,
                              void* d_out, int out_size) {
    const float* pred_locs   = (const float*)d_in[0];
    const float* pred_scores = (const float*)d_in[1];
    const float* gt_boxes    = (const float*)d_in[2];
    const int*   gt_labels   = (const int*)d_in[3];
    const float* priors      = (const float*)d_in[4];
    float* out = (float*)d_out;

    k_init<<<2, 1024>>>();
    k_prior_best<<<dim3(9, NB), 256>>>(gt_boxes, priors);
    k_obj_best<<<dim3(8, NB), 256>>>(gt_boxes, priors);
    k_assemble<<<dim3(9, NB), 256>>>(gt_boxes, gt_labels, priors, pred_locs);
    k_ce<<<(NB * NP + 7) / 8, 256>>>(pred_scores);
    k_topk<<<NB, 256>>>();
    k_final<<<1, 32>>>(out);
}

// round 6
// speedup vs baseline: 2.2832x; 2.2832x over previous
#include <cuda_runtime.h>
#include <math.h>

#define NB 64
#define NP 8732
#define NO 32
#define NC 81
#define IMGSZ 224.0f
#define THRESH 0.5f

// ---------------- scratch (device globals; reset at tail of k_final) -------
static __device__ unsigned long long g_objkey[NB * NO];   // packed (iou_bits<<32)|~p
static __device__ float          g_bestov[NB * NP];
static __device__ unsigned char  g_bestobj[NB * NP];
static __device__ unsigned char  g_label[NB * NP];
static __device__ float          g_ce[NB * NP];
static __device__ int            g_npos[NB];
static __device__ float          g_locsum[NB];
static __device__ float          g_contrib[NB];

// ---------------- helpers --------------------------------------------------
__device__ __forceinline__ float warp_sum_f(float v) {
#pragma unroll
    for (int s = 16; s; s >>= 1) v += __shfl_xor_sync(0xffffffffu, v, s);
    return v;
}
__device__ __forceinline__ int warp_sum_i(int v) {
#pragma unroll
    for (int s = 16; s; s >>= 1) v += __shfl_xor_sync(0xffffffffu, v, s);
    return v;
}
__device__ __forceinline__ float warp_max_f(float v) {
#pragma unroll
    for (int s = 16; s; s >>= 1) v = fmaxf(v, __shfl_xor_sync(0xffffffffu, v, s));
    return v;
}

// ---------------- K1: fused matching (per-prior AND per-object best) -------
// Each thread computes the 32 IoUs for its priors exactly once.
// Per-prior argmax kept in registers (first-occurrence via strict >).
// Per-object argmax via shared u64 keys (iou_bits<<32 | ~p) with a cheap
// read-prune before atomicMax; block results merged by global atomicMax.
__global__ void k_match(const float* __restrict__ gt_boxes,
                        const float* __restrict__ priors) {
    const int b = blockIdx.y;
    __shared__ float bx0[NO], by0[NO], bx1[NO], by1[NO], barea[NO];
    __shared__ unsigned long long skey[NO];
    if (threadIdx.x < NO) {
        int o = threadIdx.x;
        const float* g = gt_boxes + (b * NO + o) * 4;
        float g0 = g[0], g1 = g[1], g2 = g[2], g3 = g[3];
        float x0 = g0 / IMGSZ, y0 = g1 / IMGSZ;
        float x1 = (g0 + g2) / IMGSZ, y1 = (g1 + g3) / IMGSZ;
        bx0[o] = x0; by0[o] = y0; bx1[o] = x1; by1[o] = y1;
        barea[o] = (x1 - x0) * (y1 - y0);
        skey[o] = 0ull;
    }
    __syncthreads();

    const int stride = gridDim.x * blockDim.x;
    for (int p = blockIdx.x * blockDim.x + threadIdx.x; p < NP; p += stride) {
        float4 pr = ((const float4*)priors)[p];
        float px0 = pr.x - pr.z * 0.5f, py0 = pr.y - pr.w * 0.5f;
        float px1 = pr.x + pr.z * 0.5f, py1 = pr.y + pr.w * 0.5f;
        float parea = (px1 - px0) * (py1 - py0);
        float bv = -1.0f; int bo = 0;
        const unsigned pinv = 0xffffffffu - (unsigned)p;
#pragma unroll
        for (int o = 0; o < NO; o++) {
            float lx = fmaxf(bx0[o], px0), ly = fmaxf(by0[o], py0);
            float rx = fminf(bx1[o], px1), ry = fminf(by1[o], py1);
            float w = fmaxf(rx - lx, 0.0f), h = fmaxf(ry - ly, 0.0f);
            float inter = w * h;
            float iou = __fdividef(inter, barea[o] + parea - inter);
            if (iou > bv) { bv = iou; bo = o; }
            unsigned long long k =
                ((unsigned long long)__float_as_uint(iou) << 32) |
                (unsigned long long)pinv;
            if (k > skey[o]) atomicMax(&skey[o], k);
        }
        g_bestov[b * NP + p] = bv;
        g_bestobj[b * NP + p] = (unsigned char)bo;
    }
    __syncthreads();
    if (threadIdx.x < NO)
        atomicMax(&g_objkey[b * NO + threadIdx.x], skey[threadIdx.x]);
}

// ---------------- K2: labels + true_locs + SmoothL1 partials ---------------
__global__ void k_assemble(const float* __restrict__ gt_boxes,
                           const int* __restrict__ gt_labels,
                           const float* __restrict__ priors,
                           const float* __restrict__ pred_locs) {
    const int b = blockIdx.y;
    __shared__ float scx[NO], scy[NO], sww[NO], shh[NO];
    __shared__ int slab[NO], sforced[NO];
    __shared__ float s_loc[8];
    __shared__ int s_np[8];

    if (threadIdx.x < NO) {
        int o = threadIdx.x;
        const float* g = gt_boxes + (b * NO + o) * 4;
        float g0 = g[0], g1 = g[1], g2 = g[2], g3 = g[3];
        float x0 = g0 / IMGSZ, y0 = g1 / IMGSZ;
        float x1 = (g0 + g2) / IMGSZ, y1 = (g1 + g3) / IMGSZ;
        scx[o] = (x0 + x1) * 0.5f; scy[o] = (y0 + y1) * 0.5f;
        sww[o] = x1 - x0;          shh[o] = y1 - y0;
        slab[o] = gt_labels[b * NO + o];
        sforced[o] = (int)(0xffffffffu - (unsigned)(g_objkey[b * NO + o] & 0xffffffffull));
    }
    __syncthreads();

    float locacc = 0.0f;
    int npacc = 0;
    const int stride = gridDim.x * blockDim.x;
    for (int p = blockIdx.x * blockDim.x + threadIdx.x; p < NP; p += stride) {
        float ov = g_bestov[b * NP + p];
        int obj = g_bestobj[b * NP + p];
#pragma unroll
        for (int o = 0; o < NO; o++)
            if (sforced[o] == p) { obj = o; ov = 1.0f; }  // last o wins
        int lbl = (ov < THRESH) ? 0 : slab[obj];
        g_label[b * NP + p] = (unsigned char)lbl;
        if (lbl != 0) {
            npacc++;
            float4 pr = ((const float4*)priors)[p];
            float tcx = 10.0f * __fdividef(scx[obj] - pr.x, pr.z);
            float tcy = 10.0f * __fdividef(scy[obj] - pr.y, pr.w);
            float tw = __logf(__fdividef(sww[obj], pr.z)) * 5.0f;
            float th = __logf(__fdividef(shh[obj], pr.w)) * 5.0f;
            float4 pl = ((const float4*)pred_locs)[b * NP + p];
            float d, s = 0.0f;
            d = fabsf(pl.x - tcx); s += (d < 1.0f) ? 0.5f * d * d : d - 0.5f;
            d = fabsf(pl.y - tcy); s += (d < 1.0f) ? 0.5f * d * d : d - 0.5f;
            d = fabsf(pl.z - tw);  s += (d < 1.0f) ? 0.5f * d * d : d - 0.5f;
            d = fabsf(pl.w - th);  s += (d < 1.0f) ? 0.5f * d * d : d - 0.5f;
            locacc += s;
        }
    }
    locacc = warp_sum_f(locacc);
    npacc = warp_sum_i(npacc);
    int lane = threadIdx.x & 31, wid = threadIdx.x >> 5;
    if (lane == 0) { s_loc[wid] = locacc; s_np[wid] = npacc; }
    __syncthreads();
    if (threadIdx.x == 0) {
        float l = 0.0f; int n = 0;
        for (int k = 0; k < 8; k++) { l += s_loc[k]; n += s_np[k]; }
        atomicAdd(&g_locsum[b], l);
        atomicAdd(&g_npos[b], n);
    }
}

// ---------------- K3: per-(b,p) cross entropy (warp per row) ---------------
__global__ void k_ce(const float* __restrict__ scores) {
    const int gw = (blockIdx.x * blockDim.x + threadIdx.x) >> 5;
    const int lane = threadIdx.x & 31;
    if (gw >= NB * NP) return;
    const float* row = scores + (size_t)gw * NC;
    float x0 = row[lane];
    float x1 = row[lane + 32];                       // lane+32 <= 63 < 81 always
    bool v2 = (lane + 64) < NC;                      // lanes 0..16
    float x2 = v2 ? row[lane + 64] : -3.4e38f;
    float m = fmaxf(x0, fmaxf(x1, x2));
    m = warp_max_f(m);
    float e = __expf(x0 - m) + __expf(x1 - m) + (v2 ? __expf(x2 - m) : 0.0f);
    e = warp_sum_f(e);
    if (lane == 0) {
        int lbl = g_label[gw];
        g_ce[gw] = m + __logf(e) - row[lbl];
    }
}

// ---------------- K4: per-image hard-negative top-K sum --------------------
__global__ void k_topk() {
    __shared__ float sce[NP];             // ce_neg (clamped >= 0)
    __shared__ float s_pos[8];
    __shared__ float s_gts[8];
    __shared__ int   s_gtc[8];
    __shared__ int   s_cnt[32];

    const int b = blockIdx.x;
    const int tid = threadIdx.x, lane = tid & 31, wid = tid >> 5;

    float posacc = 0.0f;
    for (int p = tid; p < NP; p += 256) {
        float c = g_ce[b * NP + p];
        if (g_label[b * NP + p]) { posacc += c; c = 0.0f; }
        else                      c = fmaxf(c, 0.0f);
        sce[p] = c;
    }
    posacc = warp_sum_f(posacc);
    if (lane == 0) s_pos[wid] = posacc;
    if (tid < 32) s_cnt[tid] = 0;
    __syncthreads();

    int np = g_npos[b];
    int K = 3 * max(np, 1);
    if (K > NP) K = NP;

    unsigned t = 0;
    for (int bit = 31; bit >= 0; bit--) {
        unsigned cand = t | (1u << bit);
        int c = 0;
        for (int p = tid; p < NP; p += 256)
            c += (__float_as_uint(sce[p]) >= cand) ? 1 : 0;
        c = warp_sum_i(c);
        if (lane == 0) atomicAdd(&s_cnt[bit], c);
        __syncthreads();
        if (s_cnt[bit] >= K) t = cand;
    }

    float sg = 0.0f; int cg = 0;
    for (int p = tid; p < NP; p += 256) {
        unsigned u = __float_as_uint(sce[p]);
        if (u > t) { sg += sce[p]; cg++; }
    }
    sg = warp_sum_f(sg);
    cg = warp_sum_i(cg);
    if (lane == 0) { s_gts[wid] = sg; s_gtc[wid] = cg; }
    __syncthreads();

    if (tid == 0) {
        float hard = 0.0f; int c = 0; float pos = 0.0f;
        for (int k = 0; k < 8; k++) { hard += s_gts[k]; c += s_gtc[k]; pos += s_pos[k]; }
        hard += (float)(K - c) * __uint_as_float(t);
        g_contrib[b] = pos + hard;
    }
}

// ---------------- K5: final scalar + scratch reset for next replay ---------
__global__ void k_final(float* __restrict__ out) {
    const int tid = threadIdx.x;
    if (tid == 0) {
        float sumc = 0.0f, sumnpcl = 0.0f, suml = 0.0f;
        long long tp = 0;
        for (int b = 0; b < NB; b++) {
            sumc += g_contrib[b];
            int np = g_npos[b];
            tp += np;
            sumnpcl += (float)max(np, 1);
            suml += g_locsum[b];
        }
        float conf = sumc / sumnpcl;
        long long den = tp * 4; if (den < 1) den = 1;
        float loc = (tp > 0) ? (suml / (float)den) : 0.0f;
        out[0] = conf + loc;
    }
    __syncthreads();   // compute must finish before we clobber the scratch
    for (int i = tid; i < NB * NO; i += blockDim.x) g_objkey[i] = 0ull;
    if (tid < NB) { g_npos[tid] = 0; g_locsum[tid] = 0.0f; }
}

// ---------------- launch ---------------------------------------------------
extern "C" void kernel_launch(void* const* d_in, const int* in_sizes, int n_in,
                              void* d_out, int out_size) {
    const float* pred_locs   = (const float*)d_in[0];
    const float* pred_scores = (const float*)d_in[1];
    const float* gt_boxes    = (const float*)d_in[2];
    const int*   gt_labels   = (const int*)d_in[3];
    const float* priors      = (const float*)d_in[4];
    float* out = (float*)d_out;

    k_match<<<dim3(9, NB), 256>>>(gt_boxes, priors);
    k_assemble<<<dim3(9, NB), 256>>>(gt_boxes, gt_labels, priors, pred_locs);
    k_ce<<<(NB * NP * 32 + 511) / 512, 512>>>(pred_scores);
    k_topk<<<NB, 256>>>();
    k_final<<<1, 256>>>(out);
}

// round 8
// speedup vs baseline: 2.6254x; 1.1499x over previous
#include <cuda_runtime.h>
#include <math.h>

#define NB 64
#define NP 8732
#define NO 32
#define NC 81
#define IMGSZ 224.0f
#define THRESH 0.5f

// ---------------- scratch (device globals; reset at tail of k_final) -------
static __device__ unsigned long long g_objkey[NB * NO];   // packed (iou_bits<<32)|~p
static __device__ float          g_bestov[NB * NP];
static __device__ unsigned char  g_bestobj[NB * NP];
static __device__ unsigned char  g_label[NB * NP];
static __device__ float          g_ce[NB * NP];
static __device__ int            g_npos[NB];
static __device__ float          g_locsum[NB];
static __device__ float          g_contrib[NB];

// ---------------- helpers --------------------------------------------------
__device__ __forceinline__ float warp_sum_f(float v) {
#pragma unroll
    for (int s = 16; s; s >>= 1) v += __shfl_xor_sync(0xffffffffu, v, s);
    return v;
}
__device__ __forceinline__ int warp_sum_i(int v) {
#pragma unroll
    for (int s = 16; s; s >>= 1) v += __shfl_xor_sync(0xffffffffu, v, s);
    return v;
}
__device__ __forceinline__ float warp_max_f(float v) {
#pragma unroll
    for (int s = 16; s; s >>= 1) v = fmaxf(v, __shfl_xor_sync(0xffffffffu, v, s));
    return v;
}
__device__ __forceinline__ unsigned long long warp_max_ull(unsigned long long v) {
#pragma unroll
    for (int s = 16; s; s >>= 1) {
        unsigned long long o = __shfl_xor_sync(0xffffffffu, v, s);
        v = (o > v) ? o : v;
    }
    return v;
}

// ---------------- K1: fused matching (per-prior AND per-object best) -------
// Uniform trip count so full-mask warp ops are legal; per-object best via
// ballot-gated warp-max + single atomicMax per warp (rare after warm-up).
#define MATCH_BLKS 9
#define MATCH_THREADS 256
#define MATCH_STRIDE (MATCH_BLKS * MATCH_THREADS)   // 2304
#define MATCH_ITERS ((NP + MATCH_STRIDE - 1) / MATCH_STRIDE)  // 4
__global__ void k_match(const float* __restrict__ gt_boxes,
                        const float* __restrict__ priors) {
    const int b = blockIdx.y;
    __shared__ float bx0[NO], by0[NO], bx1[NO], by1[NO], barea[NO];
    __shared__ unsigned long long skey[NO];
    if (threadIdx.x < NO) {
        int o = threadIdx.x;
        const float* g = gt_boxes + (b * NO + o) * 4;
        float g0 = g[0], g1 = g[1], g2 = g[2], g3 = g[3];
        float x0 = g0 / IMGSZ, y0 = g1 / IMGSZ;
        float x1 = (g0 + g2) / IMGSZ, y1 = (g1 + g3) / IMGSZ;
        bx0[o] = x0; by0[o] = y0; bx1[o] = x1; by1[o] = y1;
        barea[o] = (x1 - x0) * (y1 - y0);
        skey[o] = 0ull;
    }
    __syncthreads();

    const int lane = threadIdx.x & 31;
#pragma unroll
    for (int it = 0; it < MATCH_ITERS; it++) {
        int p = blockIdx.x * MATCH_THREADS + threadIdx.x + it * MATCH_STRIDE;
        bool valid = p < NP;
        int pc = valid ? p : NP - 1;
        float4 pr = ((const float4*)priors)[pc];
        float px0 = pr.x - pr.z * 0.5f, py0 = pr.y - pr.w * 0.5f;
        float px1 = pr.x + pr.z * 0.5f, py1 = pr.y + pr.w * 0.5f;
        float parea = (px1 - px0) * (py1 - py0);
        float bv = -1.0f; int bo = 0;
        const unsigned long long lowbits =
            (unsigned long long)(0xffffffffu - (unsigned)pc);
#pragma unroll
        for (int o = 0; o < NO; o++) {
            float lx = fmaxf(bx0[o], px0), ly = fmaxf(by0[o], py0);
            float rx = fminf(bx1[o], px1), ry = fminf(by1[o], py1);
            float w = fmaxf(rx - lx, 0.0f), h = fmaxf(ry - ly, 0.0f);
            float inter = w * h;
            float iou = __fdividef(inter, barea[o] + parea - inter);
            if (iou > bv) { bv = iou; bo = o; }
            unsigned long long k = valid
                ? (((unsigned long long)__float_as_uint(iou) << 32) | lowbits)
                : 0ull;
            bool want = k > skey[o];
            unsigned m = __ballot_sync(0xffffffffu, want);
            if (m) {
                unsigned long long kk = want ? k : 0ull;
                kk = warp_max_ull(kk);
                if (lane == 0) atomicMax(&skey[o], kk);
            }
        }
        if (valid) {
            g_bestov[b * NP + p] = bv;
            g_bestobj[b * NP + p] = (unsigned char)bo;
        }
    }
    __syncthreads();
    if (threadIdx.x < NO)
        atomicMax(&g_objkey[b * NO + threadIdx.x], skey[threadIdx.x]);
}

// ---------------- K2: labels + true_locs + SmoothL1 partials ---------------
__global__ void k_assemble(const float* __restrict__ gt_boxes,
                           const int* __restrict__ gt_labels,
                           const float* __restrict__ priors,
                           const float* __restrict__ pred_locs) {
    const int b = blockIdx.y;
    __shared__ float scx[NO], scy[NO], sww[NO], shh[NO];
    __shared__ int slab[NO], sforced[NO];
    __shared__ float s_loc[8];
    __shared__ int s_np[8];

    if (threadIdx.x < NO) {
        int o = threadIdx.x;
        const float* g = gt_boxes + (b * NO + o) * 4;
        float g0 = g[0], g1 = g[1], g2 = g[2], g3 = g[3];
        float x0 = g0 / IMGSZ, y0 = g1 / IMGSZ;
        float x1 = (g0 + g2) / IMGSZ, y1 = (g1 + g3) / IMGSZ;
        scx[o] = (x0 + x1) * 0.5f; scy[o] = (y0 + y1) * 0.5f;
        sww[o] = x1 - x0;          shh[o] = y1 - y0;
        slab[o] = gt_labels[b * NO + o];
        sforced[o] = (int)(0xffffffffu - (unsigned)(g_objkey[b * NO + o] & 0xffffffffull));
    }
    __syncthreads();

    float locacc = 0.0f;
    int npacc = 0;
    const int stride = gridDim.x * blockDim.x;
    for (int p = blockIdx.x * blockDim.x + threadIdx.x; p < NP; p += stride) {
        float ov = g_bestov[b * NP + p];
        int obj = g_bestobj[b * NP + p];
#pragma unroll
        for (int o = 0; o < NO; o++)
            if (sforced[o] == p) { obj = o; ov = 1.0f; }  // last o wins
        int lbl = (ov < THRESH) ? 0 : slab[obj];
        g_label[b * NP + p] = (unsigned char)lbl;
        if (lbl != 0) {
            npacc++;
            float4 pr = ((const float4*)priors)[p];
            float tcx = 10.0f * __fdividef(scx[obj] - pr.x, pr.z);
            float tcy = 10.0f * __fdividef(scy[obj] - pr.y, pr.w);
            float tw = __logf(__fdividef(sww[obj], pr.z)) * 5.0f;
            float th = __logf(__fdividef(shh[obj], pr.w)) * 5.0f;
            float4 pl = ((const float4*)pred_locs)[b * NP + p];
            float d, s = 0.0f;
            d = fabsf(pl.x - tcx); s += (d < 1.0f) ? 0.5f * d * d : d - 0.5f;
            d = fabsf(pl.y - tcy); s += (d < 1.0f) ? 0.5f * d * d : d - 0.5f;
            d = fabsf(pl.z - tw);  s += (d < 1.0f) ? 0.5f * d * d : d - 0.5f;
            d = fabsf(pl.w - th);  s += (d < 1.0f) ? 0.5f * d * d : d - 0.5f;
            locacc += s;
        }
    }
    locacc = warp_sum_f(locacc);
    npacc = warp_sum_i(npacc);
    int lane = threadIdx.x & 31, wid = threadIdx.x >> 5;
    if (lane == 0) { s_loc[wid] = locacc; s_np[wid] = npacc; }
    __syncthreads();
    if (threadIdx.x == 0) {
        float l = 0.0f; int n = 0;
        for (int k = 0; k < 8; k++) { l += s_loc[k]; n += s_np[k]; }
        atomicAdd(&g_locsum[b], l);
        atomicAdd(&g_npos[b], n);
    }
}

// ---------------- K3: per-(b,p) cross entropy (warp per row) ---------------
__global__ void k_ce(const float* __restrict__ scores) {
    const int gw = (blockIdx.x * blockDim.x + threadIdx.x) >> 5;
    const int lane = threadIdx.x & 31;
    if (gw >= NB * NP) return;
    const float* row = scores + (size_t)gw * NC;
    float x0 = row[lane];
    float x1 = row[lane + 32];                       // lane+32 <= 63 < 81 always
    bool v2 = (lane + 64) < NC;                      // lanes 0..16
    float x2 = v2 ? row[lane + 64] : -3.4e38f;
    float m = fmaxf(x0, fmaxf(x1, x2));
    m = warp_max_f(m);
    float e = __expf(x0 - m) + __expf(x1 - m) + (v2 ? __expf(x2 - m) : 0.0f);
    e = warp_sum_f(e);
    if (lane == 0) {
        int lbl = g_label[gw];
        g_ce[gw] = m + __logf(e) - row[lbl];
    }
}

// ---------------- K4: per-image hard-negative top-K via radix-256 select ---
#define TK_THREADS 1024
__global__ void k_topk() {
    __shared__ float sce[NP];             // ce_neg (clamped >= 0)
    __shared__ int   hist[256];
    __shared__ float s_pos[32];
    __shared__ float s_gts[32];
    __shared__ int   s_gtc[32];
    __shared__ int   s_sel, s_kin;

    const int b = blockIdx.x;
    const int tid = threadIdx.x, lane = tid & 31, wid = tid >> 5;

    float posacc = 0.0f;
    for (int p = tid; p < NP; p += TK_THREADS) {
        float c = g_ce[b * NP + p];
        if (g_label[b * NP + p]) { posacc += c; c = 0.0f; }
        else                      c = fmaxf(c, 0.0f);
        sce[p] = c;
    }
    posacc = warp_sum_f(posacc);
    if (lane == 0) s_pos[wid] = posacc;
    __syncthreads();

    const int np = g_npos[b];
    int K = 3 * max(np, 1);
    if (K > NP) K = NP;

    // Radix select: find exact bit pattern t of the K-th largest value.
    unsigned prefix = 0;
    int Kcur = K;
#pragma unroll
    for (int pass = 0; pass < 4; pass++) {
        const int shift = 24 - pass * 8;
        const unsigned himask = (pass == 0) ? 0u : (0xffffffffu << (shift + 8));
        if (tid < 256) hist[tid] = 0;
        __syncthreads();

        // warp-aggregated histogram (uniform trip count, full-mask match)
        const int iters = (NP + TK_THREADS - 1) / TK_THREADS;  // 9
        for (int it = 0; it < iters; it++) {
            int p = it * TK_THREADS + tid;
            int key = 0x1FF;  // sentinel: no contribution
            if (p < NP) {
                unsigned u = __float_as_uint(sce[p]);
                if ((u & himask) == prefix) key = (int)((u >> shift) & 0xffu);
            }
            unsigned mm = __match_any_sync(0xffffffffu, key);
            int leader = __ffs(mm) - 1;
            if (lane == leader && key < 256)
                atomicAdd(&hist[key], __popc(mm));
        }
        __syncthreads();

        // warp 0: suffix scan over 256 bins (8 bins per lane, descending)
        if (wid == 0) {
            const int base = 255 - lane * 8;   // this lane: bins base..base-7
            int h[8]; int psum = 0;
#pragma unroll
            for (int i = 0; i < 8; i++) { h[i] = hist[base - i]; psum += h[i]; }
            int incl = psum;
#pragma unroll
            for (int s = 1; s < 32; s <<= 1) {
                int o = __shfl_up_sync(0xffffffffu, incl, s);
                if (lane >= s) incl += o;
            }
            int excl = incl - psum;            // count in bins above this segment
            if (Kcur > excl && Kcur <= excl + psum) {
                int cum = excl, sel = 0, kin = 0; bool found = false;
#pragma unroll
                for (int i = 0; i < 8; i++) {
                    if (!found && cum + h[i] >= Kcur) {
                        sel = base - i; kin = Kcur - cum; found = true;
                    }
                    cum += h[i];
                }
                s_sel = sel; s_kin = kin;
            }
        }
        __syncthreads();
        prefix |= ((unsigned)s_sel) << shift;
        Kcur = s_kin;
        __syncthreads();
    }
    const unsigned t = prefix;
    const float tf = __uint_as_float(t);

    // hard-neg sum = sum(x > t) + (K - cnt_gt) * t
    float sg = 0.0f; int cg = 0;
    for (int p = tid; p < NP; p += TK_THREADS) {
        float c = sce[p];
        if (__float_as_uint(c) > t) { sg += c; cg++; }
    }
    sg = warp_sum_f(sg);
    cg = warp_sum_i(cg);
    if (lane == 0) { s_gts[wid] = sg; s_gtc[wid] = cg; }
    __syncthreads();

    if (tid == 0) {
        float hard = 0.0f, pos = 0.0f; int c = 0;
        for (int k = 0; k < 32; k++) { hard += s_gts[k]; c += s_gtc[k]; pos += s_pos[k]; }
        hard += (float)(K - c) * tf;
        g_contrib[b] = pos + hard;
    }
}

// ---------------- K5: final scalar + scratch reset for next replay ---------
__global__ void k_final(float* __restrict__ out) {
    const int tid = threadIdx.x;
    __shared__ float s_c[2], s_ncl[2], s_l[2];
    __shared__ int s_tp[2];
    if (tid < NB) {
        float c = g_contrib[tid];
        int np = g_npos[tid];
        float ncl = (float)max(np, 1);
        float l = g_locsum[tid];
        c = warp_sum_f(c); ncl = warp_sum_f(ncl); l = warp_sum_f(l);
        int tp = warp_sum_i(np);
        if ((tid & 31) == 0) {
            int w = tid >> 5;
            s_c[w] = c; s_ncl[w] = ncl; s_l[w] = l; s_tp[w] = tp;
        }
    }
    __syncthreads();
    if (tid == 0) {
        float sumc = s_c[0] + s_c[1];
        float sumnpcl = s_ncl[0] + s_ncl[1];
        float suml = s_l[0] + s_l[1];
        long long tp = (long long)s_tp[0] + s_tp[1];
        float conf = sumc / sumnpcl;
        long long den = tp * 4; if (den < 1) den = 1;
        float loc = (tp > 0) ? (suml / (float)den) : 0.0f;
        out[0] = conf + loc;
    }
    __syncthreads();   // compute must finish before we clobber the scratch
    for (int i = tid; i < NB * NO; i += blockDim.x) g_objkey[i] = 0ull;
    if (tid < NB) { g_npos[tid] = 0; g_locsum[tid] = 0.0f; }
}

// ---------------- launch ---------------------------------------------------
extern "C" void kernel_launch(void* const* d_in, const int* in_sizes, int n_in,
                              void* d_out, int out_size) {
    const float* pred_locs   = (const float*)d_in[0];
    const float* pred_scores = (const float*)d_in[1];
    const float* gt_boxes    = (const float*)d_in[2];
    const int*   gt_labels   = (const int*)d_in[3];
    const float* priors      = (const float*)d_in[4];
    float* out = (float*)d_out;

    k_match<<<dim3(MATCH_BLKS, NB), MATCH_THREADS>>>(gt_boxes, priors);
    k_assemble<<<dim3(9, NB), 256>>>(gt_boxes, gt_labels, priors, pred_locs);
    k_ce<<<(NB * NP * 32 + 511) / 512, 512>>>(pred_scores);
    k_topk<<<NB, TK_THREADS>>>();
    k_final<<<1, 128>>>(out);
}